// round 3
// baseline (speedup 1.0000x reference)
#include <cuda_runtime.h>
#include <cstdint>

#define BS 2
#define HWC 4096            // HW channels
#define NPART 32

// scale factors
#define CWG_F  (-2.0f    / 33554432.0f)   // -CWG_STRENGTH / (BS*HW*mh*mw)
#define DCML_F (-0.01f   / 33554432.0f)   // -DCML_STRENGTH / (BS*HW*HW)
#define TV_F   (1.0e-4f  / 16128.0f)      // TV_STRENGTH / (BS*63*64*2)

__device__ float g_partial[NPART];

__device__ __forceinline__ float fsqrt_approx(float x) {
    float y; asm("sqrt.approx.f32 %0, %1;" : "=f"(y) : "f"(x)); return y;
}
__device__ __forceinline__ float fex2(float x) {
    float y; asm("ex2.approx.f32 %0, %1;" : "=f"(y) : "f"(x)); return y;
}

__global__ void init_kernel() {
    g_partial[threadIdx.x] = 0.0f;
}

// One block per (b,p) slice of sim [64x64]. Masked slices exit without
// touching sim (halves HBM traffic on average).
__global__ void __launch_bounds__(256) cwg_kernel(
    const float* __restrict__ sim,
    const float* __restrict__ wc,
    const int* __restrict__ mask)
{
    const int bp = blockIdx.x;
    if (!mask[bp]) return;

    const float wcy = wc[2 * bp + 0];
    const float wcx = wc[2 * bp + 1];
    const float4* s4 = (const float4*)(sim + (size_t)bp * 4096);

    // -0.5 * log2(e): prob = exp(-r/2) = ex2(r * K)
    const float K = -0.72134752044448169f;

    // 16 elements per thread as 4 independent float4 loads (MLP=4)
    float4 v[4];
#pragma unroll
    for (int p = 0; p < 4; p++)
        v[p] = s4[(p * 1024 + threadIdx.x * 4) >> 2];

    float acc = 0.0f;
#pragma unroll
    for (int p = 0; p < 4; p++) {
        const int idx = p * 1024 + threadIdx.x * 4;
        const float dy  = (float)(idx >> 6) - wcy;
        const float dy2 = dy * dy;
        const float dx0 = (float)(idx & 63) - wcx;
        const float dx1 = dx0 + 1.0f;
        const float dx2 = dx0 + 2.0f;
        const float dx3 = dx0 + 3.0f;
        acc += v[p].x * fex2(K * fsqrt_approx(dy2 + dx0 * dx0));
        acc += v[p].y * fex2(K * fsqrt_approx(dy2 + dx1 * dx1));
        acc += v[p].z * fex2(K * fsqrt_approx(dy2 + dx2 * dx2));
        acc += v[p].w * fex2(K * fsqrt_approx(dy2 + dx3 * dx3));
    }

    // block reduce (8 warps)
#pragma unroll
    for (int o = 16; o; o >>= 1) acc += __shfl_down_sync(0xffffffffu, acc, o);
    __shared__ float sh[8];
    if ((threadIdx.x & 31) == 0) sh[threadIdx.x >> 5] = acc;
    __syncthreads();
    if (threadIdx.x < 8) {
        float s = sh[threadIdx.x];
#pragma unroll
        for (int o = 4; o; o >>= 1) s += __shfl_down_sync(0xffu, s, o);
        if (threadIdx.x == 0)
            atomicAdd(&g_partial[blockIdx.x & (NPART - 1)], s * CWG_F);
    }
}

// 256 blocks: orientation(2) x batch(2) x line(64). Each block handles one
// row/col line: DCML ordered-pair relu terms + TV adjacent-pair terms.
__global__ void __launch_bounds__(64) tvdcml_kernel(
    const float* __restrict__ wc,
    const int* __restrict__ mask)
{
    const int t = blockIdx.x;
    const int orient = t >> 7;        // 0: row lines (vary col), 1: col lines (vary row)
    const int b      = (t >> 6) & 1;
    const int line   = t & 63;
    const int j = threadIdx.x;

    __shared__ float c0[64], c1[64], m[64];
    int p;
    if (orient == 0) p = b * HWC + line * 64 + j;   // row `line`, col j
    else             p = b * HWC + j * 64 + line;   // col `line`, row j
    c0[j] = wc[2 * p + 0];
    c1[j] = wc[2 * p + 1];
    m[j]  = mask[p] ? 1.0f : 0.0f;
    __syncthreads();

    // DCML: same-row pairs use x = cc[...,1]; same-col pairs use y = cc[...,0]
    float dc = 0.0f;
    const float vj = (orient == 0) ? c1[j] : c0[j];
    if (m[j] != 0.0f) {
        for (int q = j + 1; q < 64; q++) {
            const float vq = (orient == 0) ? c1[q] : c0[q];
            dc += fmaxf(vq - vj, 0.0f) * m[q];
        }
    }

    // TV: orientation 0 -> x-direction neighbor pairs, 1 -> y-direction
    float tv = 0.0f;
    if (j < 63) {
        const float d0 = c0[j + 1] - c0[j];
        const float d1 = c1[j + 1] - c1[j];
        tv = (d0 * d0 + d1 * d1) * m[j] * m[j + 1];
    }

    float acc = dc * DCML_F + tv * TV_F;
#pragma unroll
    for (int o = 16; o; o >>= 1) acc += __shfl_down_sync(0xffffffffu, acc, o);
    __shared__ float sh2[2];
    if ((j & 31) == 0) sh2[j >> 5] = acc;
    __syncthreads();
    if (j == 0) atomicAdd(&g_partial[t & (NPART - 1)], sh2[0] + sh2[1]);
}

__global__ void finalize_kernel(float* __restrict__ out) {
    float v = g_partial[threadIdx.x];
#pragma unroll
    for (int o = 16; o; o >>= 1) v += __shfl_down_sync(0xffffffffu, v, o);
    if (threadIdx.x == 0) out[0] = v;
}

extern "C" void kernel_launch(void* const* d_in, const int* in_sizes, int n_in,
                              void* d_out, int out_size)
{
    const float* sim  = (const float*)d_in[0];
    const float* wc   = (const float*)d_in[1];
    const int*   mask = (const int*)d_in[2];
    float* out = (float*)d_out;

    init_kernel<<<1, NPART>>>();
    cwg_kernel<<<BS * HWC, 256>>>(sim, wc, mask);
    tvdcml_kernel<<<256, 64>>>(wc, mask);
    finalize_kernel<<<1, 32>>>(out);
}

// round 4
// speedup vs baseline: 1.1484x; 1.1484x over previous
#include <cuda_runtime.h>
#include <cstdint>

#define BS 2
#define HWC 4096
#define NPART 32

#define CWG_F  (-2.0f    / 33554432.0f)   // -CWG_STRENGTH / (BS*HW*mh*mw)
#define DCML_F (-0.01f   / 33554432.0f)   // -DCML_STRENGTH / (BS*HW*HW)
#define TV_F   (1.0e-4f  / 16128.0f)      // TV_STRENGTH / (BS*63*64*2)

#define RCUT 25.0f                        // exp(-25/2)=3.7e-6 -> ~6e-5 rel truncation

__device__ float g_partial[NPART];        // zero-init at load; finalize re-zeroes

__device__ __forceinline__ float fsqrt_approx(float x) {
    float y; asm("sqrt.approx.f32 %0, %1;" : "=f"(y) : "f"(x)); return y;
}
__device__ __forceinline__ float fex2(float x) {
    float y; asm("ex2.approx.f32 %0, %1;" : "=f"(y) : "f"(x)); return y;
}

// Fused kernel: every block bp handles one [64x64] sim slice (CWG term, skipped
// when mask[bp]==0 or rows beyond the Gaussian cutoff). Blocks 0..255 also
// handle one row/col line of the TV + DCML terms.
__global__ void __launch_bounds__(256) fused_kernel(
    const float* __restrict__ sim,
    const float* __restrict__ wc,
    const int* __restrict__ mask)
{
    const int bp = blockIdx.x;
    const bool do_cwg = (mask[bp] != 0);
    const bool do_tv  = (bp < 256);
    if (!do_cwg && !do_tv) return;

    const int j = threadIdx.x;
    float total = 0.0f;

    // ---- TV + DCML (blocks 0..255; threads 0..63 active) ----
    if (do_tv) {
        __shared__ float c0[64], c1[64], m[64];
        const int orient = bp >> 7;       // 0: row lines (vary col, use x), 1: col lines (use y)
        const int b      = (bp >> 6) & 1;
        const int line   = bp & 63;
        if (j < 64) {
            int p = (orient == 0) ? (b * HWC + line * 64 + j)
                                  : (b * HWC + j * 64 + line);
            c0[j] = wc[2 * p + 0];
            c1[j] = wc[2 * p + 1];
            m[j]  = mask[p] ? 1.0f : 0.0f;
        }
        __syncthreads();
        if (j < 64) {
            float dc = 0.0f;
            const float vj = (orient == 0) ? c1[j] : c0[j];
            if (m[j] != 0.0f) {
                for (int q = j + 1; q < 64; q++) {
                    const float vq = (orient == 0) ? c1[q] : c0[q];
                    dc += fmaxf(vq - vj, 0.0f) * m[q];
                }
            }
            float tv = 0.0f;
            if (j < 63) {
                const float d0 = c0[j + 1] - c0[j];
                const float d1 = c1[j + 1] - c1[j];
                tv = (d0 * d0 + d1 * d1) * m[j] * m[j + 1];
            }
            total = dc * DCML_F + tv * TV_F;
        }
        __syncthreads();   // protect smem reuse ordering before reduce smem
    }

    // ---- CWG ----
    if (do_cwg) {
        const float wcy = wc[2 * bp + 0];
        const float wcx = wc[2 * bp + 1];
        const float4* s4 = (const float4*)(sim + (size_t)bp * 4096);
        const float K = -0.72134752044448169f;  // -0.5*log2(e)

        const int wbase = (j >> 5) << 7;        // warp's 128-element base within 1024-chunk
        const int lane4 = (j & 31) * 4;

        float acc = 0.0f;
#pragma unroll
        for (int p = 0; p < 4; p++) {
            const int idx0 = p * 1024 + wbase;            // warp-uniform
            const float r0 = (float)(idx0 >> 6);
            // nearest |dy| over this warp's two rows [r0, r0+1]
            const float dyn = fmaxf(fmaxf(r0 - wcy, wcy - (r0 + 1.0f)), 0.0f);
            if (dyn < RCUT) {
                const int idx = idx0 + lane4;
                const float4 v = s4[idx >> 2];
                const float dy  = (float)(idx >> 6) - wcy;
                const float dy2 = dy * dy;
                const float dx0 = (float)(idx & 63) - wcx;
                const float dx1 = dx0 + 1.0f;
                const float dx2 = dx0 + 2.0f;
                const float dx3 = dx0 + 3.0f;
                acc += v.x * fex2(K * fsqrt_approx(dy2 + dx0 * dx0));
                acc += v.y * fex2(K * fsqrt_approx(dy2 + dx1 * dx1));
                acc += v.z * fex2(K * fsqrt_approx(dy2 + dx2 * dx2));
                acc += v.w * fex2(K * fsqrt_approx(dy2 + dx3 * dx3));
            }
        }
        total += acc * CWG_F;
    }

    // ---- block reduce (8 warps) + one atomic ----
#pragma unroll
    for (int o = 16; o; o >>= 1) total += __shfl_down_sync(0xffffffffu, total, o);
    __shared__ float sh[8];
    if ((j & 31) == 0) sh[j >> 5] = total;
    __syncthreads();
    if (j < 8) {
        float s = sh[j];
#pragma unroll
        for (int o = 4; o; o >>= 1) s += __shfl_down_sync(0xffu, s, o);
        if (j == 0)
            atomicAdd(&g_partial[bp & (NPART - 1)], s);
    }
}

__global__ void finalize_kernel(float* __restrict__ out) {
    float v = g_partial[threadIdx.x];
    g_partial[threadIdx.x] = 0.0f;        // reset for the next graph replay
#pragma unroll
    for (int o = 16; o; o >>= 1) v += __shfl_down_sync(0xffffffffu, v, o);
    if (threadIdx.x == 0) out[0] = v;
}

extern "C" void kernel_launch(void* const* d_in, const int* in_sizes, int n_in,
                              void* d_out, int out_size)
{
    const float* sim  = (const float*)d_in[0];
    const float* wc   = (const float*)d_in[1];
    const int*   mask = (const int*)d_in[2];
    float* out = (float*)d_out;

    fused_kernel<<<BS * HWC, 256>>>(sim, wc, mask);
    finalize_kernel<<<1, 32>>>(out);
}